// round 1
// baseline (speedup 1.0000x reference)
#include <cuda_runtime.h>
#include <cuda_bf16.h>

// Problem dims
// B=4, C_IN=64, C_OUT=128, H=W=256, HO=WO=128, K=3 (9 taps), K_OFF=7
// N_PIX = 4*128*128 = 65536, KDIM = 64*9 = 576

__device__ float g_off[4 * 18 * 128 * 128];               // offset conv output
__device__ float g_col[(size_t)576 * 65536];              // im2col buffer (151 MB)

// ---------------------------------------------------------------------------
// Kernel 1: offset-predicting conv, K=7, stride=2, pad=3.
// Block = 16x16 output tile, 256 threads, 18 output channels in registers.
// ---------------------------------------------------------------------------
__global__ __launch_bounds__(256) void offset_conv_kernel(
    const float* __restrict__ x,
    const float* __restrict__ w_off,
    const float* __restrict__ b_off)
{
    __shared__ float tile[37 * 37];
    __shared__ float ws[49 * 18];

    const int b   = blockIdx.z;
    const int tx0 = blockIdx.x * 16;
    const int ty0 = blockIdx.y * 16;
    const int tid = threadIdx.x;
    const int ox_l = tid & 15;
    const int oy_l = tid >> 4;

    float acc[18];
#pragma unroll
    for (int i = 0; i < 18; i++) acc[i] = 0.f;

    const int iy0 = ty0 * 2 - 3;
    const int ix0 = tx0 * 2 - 3;

    for (int c = 0; c < 64; c++) {
        const float* xp = x + ((size_t)(b * 64 + c)) * 65536;
        for (int i = tid; i < 37 * 37; i += 256) {
            int ry = i / 37, rx = i - ry * 37;
            int iy = iy0 + ry, ix = ix0 + rx;
            float v = 0.f;
            if (iy >= 0 && iy < 256 && ix >= 0 && ix < 256) v = xp[iy * 256 + ix];
            tile[i] = v;
        }
        for (int i = tid; i < 882; i += 256) {
            int t = i / 18, oc = i - t * 18;
            ws[i] = w_off[(oc * 64 + c) * 49 + t];
        }
        __syncthreads();

#pragma unroll
        for (int ky = 0; ky < 7; ky++) {
#pragma unroll
            for (int kx = 0; kx < 7; kx++) {
                float v = tile[(oy_l * 2 + ky) * 37 + ox_l * 2 + kx];
                const int t = ky * 7 + kx;
#pragma unroll
                for (int oc = 0; oc < 18; oc++)
                    acc[oc] += v * ws[t * 18 + oc];
            }
        }
        __syncthreads();
    }

    const int oy = ty0 + oy_l, ox = tx0 + ox_l;
#pragma unroll
    for (int oc = 0; oc < 18; oc++)
        g_off[((b * 18 + oc) * 128 + oy) * 128 + ox] = acc[oc] + b_off[oc];
}

// ---------------------------------------------------------------------------
// Kernel 2: deformable bilinear gather -> im2col column buffer.
// One thread per (output pixel, tap); loops over 64 input channels.
// col[(c*9+tap)][n],  n = ((b*HO)+ho)*WO+wo
// ---------------------------------------------------------------------------
__global__ __launch_bounds__(256) void gather_kernel(const float* __restrict__ x)
{
    const int n = blockIdx.x * 256 + threadIdx.x;
    const int tap = blockIdx.y;
    if (n >= 65536) return;

    const int b   = n >> 14;
    const int rem = n & 16383;
    const int ho  = rem >> 7;
    const int wo  = rem & 127;
    const int ky  = tap / 3;
    const int kx  = tap - ky * 3;

    const float dy = g_off[((b * 18 + tap * 2 + 0) * 128 + ho) * 128 + wo];
    const float dx = g_off[((b * 18 + tap * 2 + 1) * 128 + ho) * 128 + wo];

    const float yf = (float)(ho * 2 - 1 + ky) + dy;
    const float xf = (float)(wo * 2 - 1 + kx) + dx;

    const float y0f = floorf(yf), x0f = floorf(xf);
    const int y0 = (int)y0f, x0 = (int)x0f;
    const int y1 = y0 + 1,   x1 = x0 + 1;
    const float wy1 = yf - y0f, wy0 = 1.f - wy1;
    const float wx1 = xf - x0f, wx0 = 1.f - wx1;

    const bool vy0 = (y0 >= 0) & (y0 < 256);
    const bool vy1 = (y1 >= 0) & (y1 < 256);
    const bool vx0 = (x0 >= 0) & (x0 < 256);
    const bool vx1 = (x1 >= 0) & (x1 < 256);

    const float w00 = (vy0 && vx0) ? wy0 * wx0 : 0.f;
    const float w01 = (vy0 && vx1) ? wy0 * wx1 : 0.f;
    const float w10 = (vy1 && vx0) ? wy1 * wx0 : 0.f;
    const float w11 = (vy1 && vx1) ? wy1 * wx1 : 0.f;

    const int y0c = min(max(y0, 0), 255), y1c = min(max(y1, 0), 255);
    const int x0c = min(max(x0, 0), 255), x1c = min(max(x1, 0), 255);
    const int i00 = y0c * 256 + x0c, i01 = y0c * 256 + x1c;
    const int i10 = y1c * 256 + x0c, i11 = y1c * 256 + x1c;

    const float* p = x + (size_t)b * 64 * 65536;
    const size_t outbase = (size_t)tap * 65536 + n;

#pragma unroll 4
    for (int c = 0; c < 64; c++) {
        const float* pc = p + c * 65536;
        float v = pc[i00] * w00 + pc[i01] * w01 + pc[i10] * w10 + pc[i11] * w11;
        g_col[(size_t)c * (9 * 65536) + outbase] = v;
    }
}

// ---------------------------------------------------------------------------
// Kernel 3: GEMM  out[o][n] = sum_k W[o][k] * col[k][n] + bias[o]
// M=128, N=65536, K=576.  BM=128, BN=128, BK=8, 256 threads, 8x8 microtile.
// Output scattered into NCHW layout of d_out.
// ---------------------------------------------------------------------------
__global__ __launch_bounds__(256) void gemm_kernel(
    const float* __restrict__ Wt,     // [128][576]
    const float* __restrict__ bias,   // [128]
    float* __restrict__ out)          // [4][128][16384]
{
    __shared__ float As[8][128];
    __shared__ float Bs[8][128];

    const int tid = threadIdx.x;
    const int tx  = tid & 15;
    const int ty  = tid >> 4;
    const int n0  = blockIdx.x * 128;

    float acc[8][8];
#pragma unroll
    for (int i = 0; i < 8; i++)
#pragma unroll
        for (int j = 0; j < 8; j++) acc[i][j] = 0.f;

    const int am = tid & 127;        // A row (m)
    const int ak = (tid >> 7) * 4;   // A k start: 0 or 4
    const int bk = tid >> 5;         // B row (k): 0..7
    const int bn = (tid & 31) * 4;   // B col: 0..124

    for (int k0 = 0; k0 < 576; k0 += 8) {
        float4 av = *(const float4*)(Wt + (size_t)am * 576 + k0 + ak);
        As[ak + 0][am] = av.x;
        As[ak + 1][am] = av.y;
        As[ak + 2][am] = av.z;
        As[ak + 3][am] = av.w;
        float4 bv = *(const float4*)(g_col + (size_t)(k0 + bk) * 65536 + n0 + bn);
        *(float4*)&Bs[bk][bn] = bv;
        __syncthreads();

#pragma unroll
        for (int k = 0; k < 8; k++) {
            float a[8], bfr[8];
#pragma unroll
            for (int i = 0; i < 8; i++) a[i] = As[k][ty * 8 + i];
#pragma unroll
            for (int j = 0; j < 8; j++) bfr[j] = Bs[k][tx * 8 + j];
#pragma unroll
            for (int i = 0; i < 8; i++)
#pragma unroll
                for (int j = 0; j < 8; j++) acc[i][j] += a[i] * bfr[j];
        }
        __syncthreads();
    }

    // epilogue: NCHW scatter with float4 stores (16384 % 8 == 0 so no
    // batch-boundary crossing inside a float4)
#pragma unroll
    for (int i = 0; i < 8; i++) {
        const int m = ty * 8 + i;
        const float bv = bias[m];
#pragma unroll
        for (int j4 = 0; j4 < 2; j4++) {
            const int cn = n0 + tx * 8 + j4 * 4;
            const int bb = cn >> 14;
            const int r  = cn & 16383;
            float4 v;
            v.x = acc[i][j4 * 4 + 0] + bv;
            v.y = acc[i][j4 * 4 + 1] + bv;
            v.z = acc[i][j4 * 4 + 2] + bv;
            v.w = acc[i][j4 * 4 + 3] + bv;
            *(float4*)(out + ((size_t)(bb * 128 + m)) * 16384 + r) = v;
        }
    }
}

// ---------------------------------------------------------------------------
// Kernel 4: GroupNorm, 16 groups of 8 channels. Group data is contiguous:
// block bg = b*16+g handles out[bg*131072 .. +131072).
// ---------------------------------------------------------------------------
__global__ __launch_bounds__(256) void gn_kernel(
    float* __restrict__ out,
    const float* __restrict__ gamma,
    const float* __restrict__ beta)
{
    __shared__ float s_sum[256], s_sq[256];
    const int bg  = blockIdx.x;
    const int tid = threadIdx.x;
    float* p = out + (size_t)bg * 131072;

    float sum = 0.f, sq = 0.f;
    const float4* p4 = (const float4*)p;
    for (int i = tid; i < 32768; i += 256) {
        float4 v = p4[i];
        sum += v.x + v.y + v.z + v.w;
        sq  += v.x * v.x + v.y * v.y + v.z * v.z + v.w * v.w;
    }
    s_sum[tid] = sum; s_sq[tid] = sq;
    __syncthreads();
    for (int s = 128; s > 0; s >>= 1) {
        if (tid < s) { s_sum[tid] += s_sum[tid + s]; s_sq[tid] += s_sq[tid + s]; }
        __syncthreads();
    }
    const float mu  = s_sum[0] * (1.f / 131072.f);
    const float var = s_sq[0] * (1.f / 131072.f) - mu * mu;
    const float rs  = rsqrtf(var + 1e-5f);
    const int g = bg & 15;

    float4* q4 = (float4*)p;
    for (int i = tid; i < 32768; i += 256) {
        const int ch = (g << 3) + (i >> 12);   // 4096 float4 per channel
        const float ga = gamma[ch] * rs;
        const float be = beta[ch] - mu * ga;
        float4 v = q4[i];
        v.x = v.x * ga + be; v.y = v.y * ga + be;
        v.z = v.z * ga + be; v.w = v.w * ga + be;
        q4[i] = v;
    }
}

// ---------------------------------------------------------------------------
extern "C" void kernel_launch(void* const* d_in, const int* in_sizes, int n_in,
                              void* d_out, int out_size)
{
    const float* x      = (const float*)d_in[0];
    const float* w_off  = (const float*)d_in[1];
    const float* b_off  = (const float*)d_in[2];
    const float* weight = (const float*)d_in[3];
    const float* bias   = (const float*)d_in[4];
    const float* gamma  = (const float*)d_in[5];
    const float* beta   = (const float*)d_in[6];
    float* out = (float*)d_out;

    offset_conv_kernel<<<dim3(8, 8, 4), 256>>>(x, w_off, b_off);
    gather_kernel<<<dim3(256, 9), 256>>>(x);
    gemm_kernel<<<512, 256>>>(weight, bias, out);
    gn_kernel<<<64, 256>>>(out, gamma, beta);
}

// round 2
// speedup vs baseline: 1.1309x; 1.1309x over previous
#include <cuda_runtime.h>
#include <cuda_bf16.h>

// Dims: B=4, C_IN=64, C_OUT=128, H=W=256, HO=WO=128, K=3 (9 taps), K_OFF=7
// N_PIX = 65536, KDIM = 576

// Scratch (no allocs allowed)
__device__ float g_offp[4 * 4 * 18 * 128 * 128];   // 4 channel-chunk partials of offset conv
__device__ float g_wt[576 * 128];                  // transposed deform weights: [k][m]
__device__ float g_psum[512 * 16];                 // per (b,ho)-block per-group partial sums
__device__ float g_psq[512 * 16];

// ---------------------------------------------------------------------------
// Kernel 0: transpose weight [128][576] -> g_wt[k][m] (k = c*9+t)
// ---------------------------------------------------------------------------
__global__ __launch_bounds__(256) void prep_wt_kernel(const float* __restrict__ weight)
{
    int idx = blockIdx.x * 256 + threadIdx.x;
    if (idx < 576 * 128) {
        int k = idx >> 7, m = idx & 127;
        g_wt[idx] = weight[m * 576 + k];
    }
}

// ---------------------------------------------------------------------------
// Kernel 1: offset conv (K=7, s=2, p=3), channel-split x4 partials.
// Block: 32x32 output tile, 256 threads, 2x2 pixels/thread, 18 ch in regs.
// grid (4,4,16): z = chunk*4 + b
// ---------------------------------------------------------------------------
__global__ __launch_bounds__(256) void offset_conv_kernel(
    const float* __restrict__ x,
    const float* __restrict__ w_off)
{
    __shared__ float tile[69 * 70];
    __shared__ float ws[49 * 18];

    const int b     = blockIdx.z & 3;
    const int chunk = blockIdx.z >> 2;
    const int ox0   = blockIdx.x * 32;
    const int oy0   = blockIdx.y * 32;
    const int tid   = threadIdx.x;
    const int tx    = tid & 15;
    const int ty    = tid >> 4;

    float acc[72];
#pragma unroll
    for (int i = 0; i < 72; i++) acc[i] = 0.f;

    const int iy0 = oy0 * 2 - 3;
    const int ix0 = ox0 * 2 - 3;

    for (int c = 0; c < 16; c++) {
        const int ci = chunk * 16 + c;
        const float* xp = x + ((size_t)(b * 64 + ci) << 16);
        for (int i = tid; i < 69 * 69; i += 256) {
            int r = i / 69, col = i - r * 69;
            int iy = iy0 + r, ix = ix0 + col;
            float v = 0.f;
            if (iy >= 0 && iy < 256 && ix >= 0 && ix < 256) v = xp[iy * 256 + ix];
            tile[r * 70 + col] = v;
        }
        for (int i = tid; i < 882; i += 256) {
            int t = i / 18, oc = i - t * 18;
            ws[t * 18 + oc] = w_off[(oc * 64 + ci) * 49 + t];
        }
        __syncthreads();

#pragma unroll
        for (int ky = 0; ky < 7; ky++) {
#pragma unroll
            for (int kx = 0; kx < 7; kx++) {
                const int t = ky * 7 + kx;
                float v00 = tile[(ty * 4 + 0 + ky) * 70 + tx * 4 + 0 + kx];
                float v01 = tile[(ty * 4 + 0 + ky) * 70 + tx * 4 + 2 + kx];
                float v10 = tile[(ty * 4 + 2 + ky) * 70 + tx * 4 + 0 + kx];
                float v11 = tile[(ty * 4 + 2 + ky) * 70 + tx * 4 + 2 + kx];
#pragma unroll
                for (int oc = 0; oc < 18; oc++) {
                    float w = ws[t * 18 + oc];
                    acc[oc * 4 + 0] += v00 * w;
                    acc[oc * 4 + 1] += v01 * w;
                    acc[oc * 4 + 2] += v10 * w;
                    acc[oc * 4 + 3] += v11 * w;
                }
            }
        }
        __syncthreads();
    }

    const int oy = oy0 + ty * 2, ox = ox0 + tx * 2;
#pragma unroll
    for (int oc = 0; oc < 18; oc++) {
        float* op = g_offp + ((size_t)((chunk * 4 + b) * 18 + oc) << 14);
        op[(oy + 0) * 128 + ox + 0] = acc[oc * 4 + 0];
        op[(oy + 0) * 128 + ox + 1] = acc[oc * 4 + 1];
        op[(oy + 1) * 128 + ox + 0] = acc[oc * 4 + 2];
        op[(oy + 1) * 128 + ox + 1] = acc[oc * 4 + 3];
    }
}

// ---------------------------------------------------------------------------
// Kernel 2: fused deformable gather + GEMM + bias + GN partial stats.
// Block bx handles output row (b,ho) = one 128-pixel row, all 128 out chans.
// Per input channel c: load 14x256 x-window to smem, build 9x128 B tile by
// bilinear gather (metadata precomputed once), 9 FMA k-steps (8x8 microtile).
// ---------------------------------------------------------------------------
__global__ __launch_bounds__(256) void fused_kernel(
    const float* __restrict__ x,
    const float* __restrict__ b_off,
    const float* __restrict__ bias,
    float* __restrict__ out)
{
    __shared__ float  xwin[14 * 256];
    __shared__ float  As[1152];     // [t][m]
    __shared__ float  Bs[1152];     // [t][pix]
    __shared__ float4 mw[1152];     // (ay0, ay1, ax0, ax1)
    __shared__ int    mi[1152];     // i00 | (xd<<16)

    const int tid = threadIdx.x;
    const int tx  = tid & 15;
    const int ty  = tid >> 4;
    const int bx  = blockIdx.x;
    const int n0  = bx * 128;
    const int b   = n0 >> 14;
    const int ho  = (n0 >> 7) & 127;
    const int yb  = 2 * ho - 6;          // window base row

    // ---- precompute gather metadata for 9 taps x 128 pixels ----
    for (int i = tid; i < 1152; i += 256) {
        const int tap = i >> 7;
        const int wo  = i & 127;
        const int ky  = tap / 3;
        const int kx  = tap - ky * 3;

        const int hw = ho * 128 + wo;
        float dy = b_off[tap * 2 + 0];
        float dx = b_off[tap * 2 + 1];
#pragma unroll
        for (int p = 0; p < 4; p++) {
            dy += g_offp[((size_t)((p * 4 + b) * 18 + tap * 2 + 0) << 14) + hw];
            dx += g_offp[((size_t)((p * 4 + b) * 18 + tap * 2 + 1) << 14) + hw];
        }

        const float yf = (float)(2 * ho - 1 + ky) + dy;
        const float xf = (float)(2 * wo - 1 + kx) + dx;
        const float y0f = floorf(yf), x0f = floorf(xf);
        const int y0 = (int)y0f, x0 = (int)x0f;
        const float wy1 = yf - y0f, wy0 = 1.f - wy1;
        const float wx1 = xf - x0f, wx0 = 1.f - wx1;

        const bool vy0 = (y0 >= 0) & (y0 < 256);
        const bool vy1 = (y0 + 1 >= 0) & (y0 + 1 < 256);
        const bool vx0 = (x0 >= 0) & (x0 < 256);
        const bool vx1 = (x0 + 1 >= 0) & (x0 + 1 < 256);

        float4 w;
        w.x = vy0 ? wy0 : 0.f;   // ay0
        w.y = vy1 ? wy1 : 0.f;   // ay1
        w.z = vx0 ? wx0 : 0.f;   // ax0
        w.w = vx1 ? wx1 : 0.f;   // ax1
        mw[i] = w;

        int wy = y0 - yb;
        wy = min(max(wy, 0), 12);
        const int x0c = min(max(x0, 0), 255);
        const int x1c = min(max(x0 + 1, 0), 255);
        mi[i] = (wy * 256 + x0c) | ((x1c - x0c) << 16);
    }

    float acc[8][8];
#pragma unroll
    for (int i = 0; i < 8; i++)
#pragma unroll
        for (int j = 0; j < 8; j++) acc[i][j] = 0.f;

    const float* xb = x + ((size_t)b << 22);   // b*64*65536

    for (int c = 0; c < 64; c++) {
        __syncthreads();
        // load x window (14 rows x 256 cols), zero-padded outside image
        {
            const float4* xc4 = (const float4*)(xb + ((size_t)c << 16));
            for (int i = tid; i < 14 * 64; i += 256) {
                const int r = i >> 6;          // window row
                const int q = i & 63;          // float4 col
                const int y = yb + r;
                float4 v = make_float4(0.f, 0.f, 0.f, 0.f);
                if (y >= 0 && y < 256) v = xc4[y * 64 + q];
                *(float4*)&xwin[r * 256 + q * 4] = v;
            }
        }
        // load A slab: g_wt[c*1152 .. +1152) contiguous
        {
            const float4* wp = (const float4*)(g_wt + (size_t)c * 1152);
            for (int i = tid; i < 288; i += 256)
                *(float4*)&As[i * 4] = wp[i];
        }
        __syncthreads();

        // build B tile by bilinear gather from the smem window
        for (int i = tid; i < 1152; i += 256) {
            const float4 w = mw[i];
            const int mm = mi[i];
            const int i00 = mm & 0xFFFF;
            const int i01 = i00 + (mm >> 16);
            const float top = w.z * xwin[i00]       + w.w * xwin[i01];
            const float bot = w.z * xwin[i00 + 256] + w.w * xwin[i01 + 256];
            Bs[i] = w.x * top + w.y * bot;
        }
        __syncthreads();

        // 9 FMA k-steps
#pragma unroll
        for (int k = 0; k < 9; k++) {
            float4 a0 = *(const float4*)&As[k * 128 + ty * 8];
            float4 a1 = *(const float4*)&As[k * 128 + ty * 8 + 4];
            float4 b0 = *(const float4*)&Bs[k * 128 + tx * 8];
            float4 b1 = *(const float4*)&Bs[k * 128 + tx * 8 + 4];
            const float a[8] = {a0.x, a0.y, a0.z, a0.w, a1.x, a1.y, a1.z, a1.w};
            const float bb[8] = {b0.x, b0.y, b0.z, b0.w, b1.x, b1.y, b1.z, b1.w};
#pragma unroll
            for (int ii = 0; ii < 8; ii++)
#pragma unroll
                for (int jj = 0; jj < 8; jj++) acc[ii][jj] += a[ii] * bb[jj];
        }
    }

    // ---- epilogue: bias, output store, GN partial stats ----
    float s = 0.f, sq = 0.f;
#pragma unroll
    for (int i = 0; i < 8; i++) {
        const int m = ty * 8 + i;
        const float bv = bias[m];
        float4 v0, v1;
        v0.x = acc[i][0] + bv; v0.y = acc[i][1] + bv;
        v0.z = acc[i][2] + bv; v0.w = acc[i][3] + bv;
        v1.x = acc[i][4] + bv; v1.y = acc[i][5] + bv;
        v1.z = acc[i][6] + bv; v1.w = acc[i][7] + bv;
        s  += v0.x + v0.y + v0.z + v0.w + v1.x + v1.y + v1.z + v1.w;
        sq += v0.x*v0.x + v0.y*v0.y + v0.z*v0.z + v0.w*v0.w
            + v1.x*v1.x + v1.y*v1.y + v1.z*v1.z + v1.w*v1.w;
        float* op = out + (((size_t)(b * 128 + m)) << 14) + ho * 128 + tx * 8;
        *(float4*)op = v0;
        *(float4*)(op + 4) = v1;
    }
    // reduce across the 16 tx lanes of each ty (lanes contiguous within warp)
#pragma unroll
    for (int off = 8; off > 0; off >>= 1) {
        s  += __shfl_down_sync(0xffffffffu, s,  off, 16);
        sq += __shfl_down_sync(0xffffffffu, sq, off, 16);
    }
    if (tx == 0) {
        g_psum[bx * 16 + ty] = s;   // ty == group index (m/8 with m=ty*8+i)
        g_psq [bx * 16 + ty] = sq;
    }
}

// ---------------------------------------------------------------------------
// Kernel 3: GroupNorm finalize. 512 blocks; block = one (b, group, channel).
// Reduces the 128 per-row partials for its group, then normalizes 16384 elems.
// ---------------------------------------------------------------------------
__global__ __launch_bounds__(256) void gn_final_kernel(
    float* __restrict__ out,
    const float* __restrict__ gamma,
    const float* __restrict__ beta)
{
    __shared__ float rs[128], rq[128];
    const int tid  = threadIdx.x;
    const int g64  = blockIdx.x >> 3;       // b*16+g
    const int part = blockIdx.x & 7;        // channel within group
    const int b    = g64 >> 4;
    const int g    = g64 & 15;

    if (tid < 128) {
        rs[tid] = g_psum[(b * 128 + tid) * 16 + g];
        rq[tid] = g_psq [(b * 128 + tid) * 16 + g];
    }
    __syncthreads();
    for (int s = 64; s > 0; s >>= 1) {
        if (tid < s) { rs[tid] += rs[tid + s]; rq[tid] += rq[tid + s]; }
        __syncthreads();
    }
    const float mu   = rs[0] * (1.f / 131072.f);
    const float var  = rq[0] * (1.f / 131072.f) - mu * mu;
    const float rsig = rsqrtf(var + 1e-5f);

    const int ch = g * 8 + part;
    const float ga = gamma[ch] * rsig;
    const float be = beta[ch] - mu * ga;

    float4* p = (float4*)(out + (((size_t)(b * 128 + ch)) << 14));
    for (int i = tid; i < 4096; i += 256) {
        float4 v = p[i];
        v.x = v.x * ga + be; v.y = v.y * ga + be;
        v.z = v.z * ga + be; v.w = v.w * ga + be;
        p[i] = v;
    }
}

// ---------------------------------------------------------------------------
extern "C" void kernel_launch(void* const* d_in, const int* in_sizes, int n_in,
                              void* d_out, int out_size)
{
    const float* x      = (const float*)d_in[0];
    const float* w_off  = (const float*)d_in[1];
    const float* b_off  = (const float*)d_in[2];
    const float* weight = (const float*)d_in[3];
    const float* bias   = (const float*)d_in[4];
    const float* gamma  = (const float*)d_in[5];
    const float* beta   = (const float*)d_in[6];
    float* out = (float*)d_out;

    prep_wt_kernel<<<288, 256>>>(weight);
    offset_conv_kernel<<<dim3(4, 4, 16), 256>>>(x, w_off);
    fused_kernel<<<512, 256>>>(x, b_off, bias, out);
    gn_final_kernel<<<512, 256>>>(out, gamma, beta);
}

// round 4
// speedup vs baseline: 1.5519x; 1.3723x over previous
#include <cuda_runtime.h>
#include <cuda_bf16.h>
#include <cstdint>

// Dims: B=4, C_IN=64, C_OUT=128, H=W=256, HO=WO=128, K=3 (9 taps), K_OFF=7

// ---------------- scratch ----------------
__device__ float g_offp[4 * 4 * 18 * 128 * 128];   // offset-conv channel-chunk partials
__device__ float g_wtA[64 * 128 * 16];             // A tiles (tf32-rounded): [c][m][16]
__device__ float g_psum[512 * 16];
__device__ float g_psq[512 * 16];

// ---------------- helpers ----------------
__device__ __forceinline__ uint32_t smem_u32(const void* p) {
    uint32_t a;
    asm("{ .reg .u64 t; cvta.to.shared.u64 t, %1; cvt.u32.u64 %0, t; }" : "=r"(a) : "l"(p));
    return a;
}
__device__ __forceinline__ uint32_t f2tf32(float f) {
    uint32_t u;
    asm("cvt.rna.tf32.f32 %0, %1;" : "=r"(u) : "f"(f));
    return u;
}
__device__ __forceinline__ void mma_tf32(float* d, uint32_t a0, uint32_t a1,
                                         uint32_t a2, uint32_t a3,
                                         uint32_t b0, uint32_t b1) {
    asm volatile(
        "mma.sync.aligned.m16n8k8.row.col.f32.tf32.tf32.f32 "
        "{%0,%1,%2,%3}, {%4,%5,%6,%7}, {%8,%9}, {%0,%1,%2,%3};"
        : "+f"(d[0]), "+f"(d[1]), "+f"(d[2]), "+f"(d[3])
        : "r"(a0), "r"(a1), "r"(a2), "r"(a3), "r"(b0), "r"(b1));
}

#define CPA16(dst, src, sz) \
    asm volatile("cp.async.cg.shared.global [%0], [%1], 16, %2;" :: "r"(dst), "l"(src), "r"(sz))
#define CPA_COMMIT() asm volatile("cp.async.commit_group;" ::: "memory")
#define CPA_WAIT0()  asm volatile("cp.async.wait_group 0;" ::: "memory")

// ---------------------------------------------------------------------------
// Kernel 0: A-tile prep: g_wtA[c][m][kk] = tf32(weight[m][c*9+kk]) | 0 pad
// ---------------------------------------------------------------------------
__global__ __launch_bounds__(256) void prep_wt_kernel(const float* __restrict__ weight)
{
    int idx = blockIdx.x * 256 + threadIdx.x;       // 131072 total
    int c  = idx >> 11;
    int m  = (idx >> 4) & 127;
    int kk = idx & 15;
    float v = (kk < 9) ? weight[m * 576 + c * 9 + kk] : 0.f;
    g_wtA[idx] = __uint_as_float(f2tf32(v));
}

// ---------------------------------------------------------------------------
// Kernel 1: offset conv (K=7, s=2, p=3), channel-split x4 partials (SIMT fp32).
// ---------------------------------------------------------------------------
__global__ __launch_bounds__(256) void offset_conv_kernel(
    const float* __restrict__ x,
    const float* __restrict__ w_off)
{
    __shared__ float tile[69 * 70];
    __shared__ float ws[49 * 20];

    const int b     = blockIdx.z & 3;
    const int chunk = blockIdx.z >> 2;
    const int ox0   = blockIdx.x * 32;
    const int oy0   = blockIdx.y * 32;
    const int tid   = threadIdx.x;
    const int tx    = tid & 15;
    const int ty    = tid >> 4;

    float acc[72];
#pragma unroll
    for (int i = 0; i < 72; i++) acc[i] = 0.f;

    const int iy0 = oy0 * 2 - 3;
    const int ix0 = ox0 * 2 - 3;

    for (int c = 0; c < 16; c++) {
        const int ci = chunk * 16 + c;
        const float* xp = x + ((size_t)(b * 64 + ci) << 16);
        for (int i = tid; i < 69 * 69; i += 256) {
            int r = i / 69, col = i - r * 69;
            int iy = iy0 + r, ix = ix0 + col;
            float v = 0.f;
            if (iy >= 0 && iy < 256 && ix >= 0 && ix < 256) v = xp[iy * 256 + ix];
            tile[r * 70 + col] = v;
        }
        for (int i = tid; i < 882; i += 256) {
            int t = i / 18, oc = i - t * 18;
            ws[t * 20 + oc] = w_off[(oc * 64 + ci) * 49 + t];
        }
        __syncthreads();

#pragma unroll
        for (int ky = 0; ky < 7; ky++) {
#pragma unroll
            for (int kx = 0; kx < 7; kx++) {
                const int t = ky * 7 + kx;
                const float v00 = tile[(ty * 4 + 0 + ky) * 70 + tx * 4 + 0 + kx];
                const float v01 = tile[(ty * 4 + 0 + ky) * 70 + tx * 4 + 2 + kx];
                const float v10 = tile[(ty * 4 + 2 + ky) * 70 + tx * 4 + 0 + kx];
                const float v11 = tile[(ty * 4 + 2 + ky) * 70 + tx * 4 + 2 + kx];
                const float* wp = &ws[t * 20];
#pragma unroll
                for (int q = 0; q < 4; q++) {
                    const float4 w = *(const float4*)(wp + q * 4);
                    const float wv[4] = {w.x, w.y, w.z, w.w};
#pragma unroll
                    for (int j = 0; j < 4; j++) {
                        const int oc = q * 4 + j;
                        acc[oc * 4 + 0] += v00 * wv[j];
                        acc[oc * 4 + 1] += v01 * wv[j];
                        acc[oc * 4 + 2] += v10 * wv[j];
                        acc[oc * 4 + 3] += v11 * wv[j];
                    }
                }
#pragma unroll
                for (int j = 0; j < 2; j++) {
                    const int oc = 16 + j;
                    const float w = wp[oc];
                    acc[oc * 4 + 0] += v00 * w;
                    acc[oc * 4 + 1] += v01 * w;
                    acc[oc * 4 + 2] += v10 * w;
                    acc[oc * 4 + 3] += v11 * w;
                }
            }
        }
        __syncthreads();
    }

    const int oy = oy0 + ty * 2, ox = ox0 + tx * 2;
#pragma unroll
    for (int oc = 0; oc < 18; oc++) {
        float* op = g_offp + ((size_t)((chunk * 4 + b) * 18 + oc) << 14);
        op[(oy + 0) * 128 + ox + 0] = acc[oc * 4 + 0];
        op[(oy + 0) * 128 + ox + 1] = acc[oc * 4 + 1];
        op[(oy + 1) * 128 + ox + 0] = acc[oc * 4 + 2];
        op[(oy + 1) * 128 + ox + 1] = acc[oc * 4 + 3];
    }
}

// ---------------------------------------------------------------------------
// Kernel 2: fused deformable gather + TF32 mma.sync GEMM + bias + GN partials.
// Block = one (b,ho) row: M=128 oc x N=128 pix; K = 64 ch x 16 taps (9+7 pad).
// 8 warps: 2 m-groups x 4 n-groups, warp tile 64x32, m16n8k8 fragments.
// Tiles stored stride-20 floats -> conflict-free fragment LDS.
// ---------------------------------------------------------------------------
#define WIN0_OFF   0
#define WIN1_OFF   14336
#define BS_OFF     28672     // 128 x 20 floats = 10240 B (single buffer)
#define AS0_OFF    38912     // 128 x 20 floats
#define AS1_OFF    49152
#define MW_OFF     59392     // float4[1152] = 18432 B (reused for partials in epilogue)
#define MI_OFF     77824     // int[1152] = 4608 B
#define FUSED_SMEM 82432

__global__ __launch_bounds__(256, 2) void fused_kernel(
    const float* __restrict__ x,
    const float* __restrict__ b_off,
    const float* __restrict__ bias,
    float* __restrict__ out)
{
    extern __shared__ char smem[];
    const uint32_t su = smem_u32(smem);
    const int tid = threadIdx.x;
    const int wid = tid >> 5;
    const int l   = tid & 31;
    const int bx  = blockIdx.x;
    const int b   = bx >> 7;
    const int ho  = bx & 127;
    const int yb  = 2 * ho - 6;

    float4* mw = (float4*)(smem + MW_OFF);
    int*    mi = (int*)(smem + MI_OFF);
    uint32_t* Bs = (uint32_t*)(smem + BS_OFF);

    const float* xb = x + ((size_t)b << 22);

    // ---- prefetch channel 0 (window + A) into buffer 0 ----
    {
        for (int i = tid; i < 896; i += 256) {
            const int r = i >> 6, q = i & 63;
            const int y = yb + r;
            const int yc = min(max(y, 0), 255);
            const uint32_t sz = (y >= 0 && y < 256) ? 16u : 0u;
            CPA16(su + WIN0_OFF + (i << 4), xb + yc * 256 + q * 4, sz);
        }
        for (int i = tid; i < 512; i += 256) {
            const int m = i >> 2, j = i & 3;
            CPA16(su + AS0_OFF + (uint32_t)(m * 80 + j * 16), g_wtA + i * 4, 16u);
        }
        CPA_COMMIT();
    }

    // ---- zero B tap-pad (kk 9..15), written once, never overwritten ----
    for (int i = tid; i < 128 * 7; i += 256) {
        const int p  = i / 7;
        const int kk = 9 + (i - p * 7);
        Bs[p * 20 + kk] = 0u;
    }

    // ---- gather metadata: 9 taps x 128 pixels ----
    for (int i = tid; i < 1152; i += 256) {
        const int tap = i >> 7;
        const int wo  = i & 127;
        const int ky  = tap / 3;
        const int kx  = tap - ky * 3;
        const int hw  = ho * 128 + wo;

        float dy = b_off[tap * 2 + 0];
        float dx = b_off[tap * 2 + 1];
#pragma unroll
        for (int p = 0; p < 4; p++) {
            dy += g_offp[((size_t)((p * 4 + b) * 18 + tap * 2 + 0) << 14) + hw];
            dx += g_offp[((size_t)((p * 4 + b) * 18 + tap * 2 + 1) << 14) + hw];
        }
        const float yf = (float)(2 * ho - 1 + ky) + dy;
        const float xf = (float)(2 * wo - 1 + kx) + dx;
        const float y0f = floorf(yf), x0f = floorf(xf);
        const int y0 = (int)y0f, x0 = (int)x0f;
        const float wy1 = yf - y0f, wy0 = 1.f - wy1;
        const float wx1 = xf - x0f, wx0 = 1.f - wx1;

        float4 w;
        w.x = ((y0 >= 0) & (y0 < 256))         ? wy0 : 0.f;
        w.y = ((y0 + 1 >= 0) & (y0 + 1 < 256)) ? wy1 : 0.f;
        w.z = ((x0 >= 0) & (x0 < 256))         ? wx0 : 0.f;
        w.w = ((x0 + 1 >= 0) & (x0 + 1 < 256)) ? wx1 : 0.f;
        mw[i] = w;

        int wy = min(max(y0 - yb, 0), 12);
        const int x0c = min(max(x0, 0), 255);
        const int x1c = min(max(x0 + 1, 0), 255);
        mi[i] = (wy * 256 + x0c) | ((x1c - x0c) << 16);
    }

    // ---- accumulators ----
    float acc[4][4][4];
#pragma unroll
    for (int i = 0; i < 4; i++)
#pragma unroll
        for (int j = 0; j < 4; j++)
#pragma unroll
            for (int q = 0; q < 4; q++) acc[i][j][q] = 0.f;

    const int mg = wid & 1;        // m-group: rows mg*64..+63
    const int ng = wid >> 1;       // n-group: cols ng*32..+31
    const int lq = l >> 2;         // 0..7
    const int lr = l & 3;          // 0..3

    // ---- mainloop over 64 channels ----
    for (int c = 0; c < 64; c++) {
        CPA_WAIT0();
        __syncthreads();   // win(c)/A(c) visible; Bs & win/A[(c+1)&1] free

        if (c + 1 < 64) {
            const float* xc = xb + ((size_t)(c + 1) << 16);
            const uint32_t wdst = su + (((c + 1) & 1) ? WIN1_OFF : WIN0_OFF);
            for (int i = tid; i < 896; i += 256) {
                const int r = i >> 6, q = i & 63;
                const int y = yb + r;
                const int yc = min(max(y, 0), 255);
                const uint32_t sz = (y >= 0 && y < 256) ? 16u : 0u;
                CPA16(wdst + (i << 4), xc + yc * 256 + q * 4, sz);
            }
            const uint32_t adst = su + (((c + 1) & 1) ? AS1_OFF : AS0_OFF);
            const float* asrc = g_wtA + (size_t)(c + 1) * 2048;
            for (int i = tid; i < 512; i += 256) {
                const int m = i >> 2, j = i & 3;
                CPA16(adst + (uint32_t)(m * 80 + j * 16), asrc + i * 4, 16u);
            }
            CPA_COMMIT();
        }

        // gather B(c) from window
        const float* win = (const float*)(smem + ((c & 1) ? WIN1_OFF : WIN0_OFF));
        for (int i = tid; i < 1152; i += 256) {
            const float4 w = mw[i];
            const int mm = mi[i];
            const int i00 = mm & 0xFFFF;
            const int i01 = i00 + (mm >> 16);
            const float top = w.z * win[i00]       + w.w * win[i01];
            const float bot = w.z * win[i00 + 256] + w.w * win[i01 + 256];
            const int p  = i & 127;
            const int kk = i >> 7;
            Bs[p * 20 + kk] = f2tf32(w.x * top + w.y * bot);
        }
        __syncthreads();   // B(c) complete, A(c) loaded

        const uint32_t* As = (const uint32_t*)(smem + ((c & 1) ? AS1_OFF : AS0_OFF));

#pragma unroll
        for (int ks = 0; ks < 2; ks++) {
            const int k0 = ks * 8;
            uint32_t a0[4], a1[4], a2[4], a3[4], b0[4], b1[4];
#pragma unroll
            for (int mt = 0; mt < 4; mt++) {
                const int row = mg * 64 + mt * 16 + lq;
                a0[mt] = As[row * 20 + k0 + lr];
                a1[mt] = As[(row + 8) * 20 + k0 + lr];
                a2[mt] = As[row * 20 + k0 + 4 + lr];
                a3[mt] = As[(row + 8) * 20 + k0 + 4 + lr];
            }
#pragma unroll
            for (int nt = 0; nt < 4; nt++) {
                const int nr = ng * 32 + nt * 8 + lq;
                b0[nt] = Bs[nr * 20 + k0 + lr];
                b1[nt] = Bs[nr * 20 + k0 + 4 + lr];
            }
#pragma unroll
            for (int mt = 0; mt < 4; mt++)
#pragma unroll
                for (int nt = 0; nt < 4; nt++)
                    mma_tf32(acc[mt][nt], a0[mt], a1[mt], a2[mt], a3[mt],
                             b0[nt], b1[nt]);
        }
    }

    // ---- epilogue: bias, store, GN partials ----
    __syncthreads();                       // metadata region now reusable
    float* ps = (float*)(smem + MW_OFF);   // [8 warps][8 slots]
    float* pq = ps + 64;

#pragma unroll
    for (int mt = 0; mt < 4; mt++) {
        const int m0 = mg * 64 + mt * 16 + lq;
        const float bv0 = bias[m0];
        const float bv1 = bias[m0 + 8];
        float s0 = 0.f, q0 = 0.f, s1 = 0.f, q1 = 0.f;
#pragma unroll
        for (int nt = 0; nt < 4; nt++) {
            const int col = ng * 32 + nt * 8 + 2 * lr;
            float v0 = acc[mt][nt][0] + bv0;
            float v1 = acc[mt][nt][1] + bv0;
            float v2 = acc[mt][nt][2] + bv1;
            float v3 = acc[mt][nt][3] + bv1;
            s0 += v0 + v1; q0 += v0 * v0 + v1 * v1;
            s1 += v2 + v3; q1 += v2 * v2 + v3 * v3;
            float2 u0 = make_float2(v0, v1);
            float2 u1 = make_float2(v2, v3);
            *(float2*)(out + (((size_t)(b * 128 + m0)) << 14) + ho * 128 + col) = u0;
            *(float2*)(out + (((size_t)(b * 128 + m0 + 8)) << 14) + ho * 128 + col) = u1;
        }
#pragma unroll
        for (int off = 16; off > 0; off >>= 1) {
            s0 += __shfl_xor_sync(0xffffffffu, s0, off);
            q0 += __shfl_xor_sync(0xffffffffu, q0, off);
            s1 += __shfl_xor_sync(0xffffffffu, s1, off);
            q1 += __shfl_xor_sync(0xffffffffu, q1, off);
        }
        if (l == 0) {
            ps[wid * 8 + mt * 2 + 0] = s0;
            pq[wid * 8 + mt * 2 + 0] = q0;
            ps[wid * 8 + mt * 2 + 1] = s1;
            pq[wid * 8 + mt * 2 + 1] = q1;
        }
    }
    __syncthreads();
    if (tid < 16) {
        const int g = tid;
        const int gm = g >> 3;     // which m-group
        const int slot = g & 7;
        float S = 0.f, Q = 0.f;
#pragma unroll
        for (int j = 0; j < 4; j++) {
            const int w = gm + j * 2;
            S += ps[w * 8 + slot];
            Q += pq[w * 8 + slot];
        }
        g_psum[bx * 16 + g] = S;
        g_psq [bx * 16 + g] = Q;
    }
}

// ---------------------------------------------------------------------------
// Kernel 3: GroupNorm finalize.
// ---------------------------------------------------------------------------
__global__ __launch_bounds__(256) void gn_final_kernel(
    float* __restrict__ out,
    const float* __restrict__ gamma,
    const float* __restrict__ beta)
{
    __shared__ float rs[128], rq[128];
    const int tid  = threadIdx.x;
    const int g64  = blockIdx.x >> 3;
    const int part = blockIdx.x & 7;
    const int b    = g64 >> 4;
    const int g    = g64 & 15;

    if (tid < 128) {
        rs[tid] = g_psum[(b * 128 + tid) * 16 + g];
        rq[tid] = g_psq [(b * 128 + tid) * 16 + g];
    }
    __syncthreads();
    for (int s = 64; s > 0; s >>= 1) {
        if (tid < s) { rs[tid] += rs[tid + s]; rq[tid] += rq[tid + s]; }
        __syncthreads();
    }
    const float mu   = rs[0] * (1.f / 131072.f);
    const float var  = rq[0] * (1.f / 131072.f) - mu * mu;
    const float rsig = rsqrtf(var + 1e-5f);

    const int ch = g * 8 + part;
    const float ga = gamma[ch] * rsig;
    const float be = beta[ch] - mu * ga;

    float4* p = (float4*)(out + (((size_t)(b * 128 + ch)) << 14));
    for (int i = tid; i < 4096; i += 256) {
        float4 v = p[i];
        v.x = v.x * ga + be; v.y = v.y * ga + be;
        v.z = v.z * ga + be; v.w = v.w * ga + be;
        p[i] = v;
    }
}

// ---------------------------------------------------------------------------
extern "C" void kernel_launch(void* const* d_in, const int* in_sizes, int n_in,
                              void* d_out, int out_size)
{
    const float* x      = (const float*)d_in[0];
    const float* w_off  = (const float*)d_in[1];
    const float* b_off  = (const float*)d_in[2];
    const float* weight = (const float*)d_in[3];
    const float* bias   = (const float*)d_in[4];
    const float* gamma  = (const float*)d_in[5];
    const float* beta   = (const float*)d_in[6];
    float* out = (float*)d_out;

    cudaFuncSetAttribute(fused_kernel,
                         cudaFuncAttributeMaxDynamicSharedMemorySize, FUSED_SMEM);

    prep_wt_kernel<<<512, 256>>>(weight);
    offset_conv_kernel<<<dim3(4, 4, 16), 256>>>(x, w_off);
    fused_kernel<<<512, 256, FUSED_SMEM>>>(x, b_off, bias, out);
    gn_final_kernel<<<512, 256>>>(out, gamma, beta);
}

// round 5
// speedup vs baseline: 1.8613x; 1.1994x over previous
#include <cuda_runtime.h>
#include <cuda_bf16.h>
#include <cstdint>

// Dims: B=4, C_IN=64, C_OUT=128, H=W=256, HO=WO=128, K=3 (9 taps), K_OFF=7

// ---------------- scratch ----------------
__device__ float g_offp[4 * 4 * 18 * 128 * 128];   // offset-conv channel-chunk partials
__device__ float g_wtA[16 * 128 * 44];             // A tiles: [group][m][44] (36 taps + pad)
__device__ float g_psum[512 * 16];
__device__ float g_psq[512 * 16];

// ---------------- helpers ----------------
__device__ __forceinline__ uint32_t smem_u32(const void* p) {
    uint32_t a;
    asm("{ .reg .u64 t; cvta.to.shared.u64 t, %1; cvt.u32.u64 %0, t; }" : "=r"(a) : "l"(p));
    return a;
}
__device__ __forceinline__ uint32_t f2tf32(float f) {
    uint32_t u;
    asm("cvt.rna.tf32.f32 %0, %1;" : "=r"(u) : "f"(f));
    return u;
}
__device__ __forceinline__ void mma_tf32(float* d, uint32_t a0, uint32_t a1,
                                         uint32_t a2, uint32_t a3,
                                         uint32_t b0, uint32_t b1) {
    asm volatile(
        "mma.sync.aligned.m16n8k8.row.col.f32.tf32.tf32.f32 "
        "{%0,%1,%2,%3}, {%4,%5,%6,%7}, {%8,%9}, {%0,%1,%2,%3};"
        : "+f"(d[0]), "+f"(d[1]), "+f"(d[2]), "+f"(d[3])
        : "r"(a0), "r"(a1), "r"(a2), "r"(a3), "r"(b0), "r"(b1));
}
__device__ __forceinline__ unsigned long long packf2(float lo, float hi) {
    unsigned long long r;
    asm("mov.b64 %0, {%1, %2};" : "=l"(r) : "f"(lo), "f"(hi));
    return r;
}
__device__ __forceinline__ void fma2(unsigned long long& acc, unsigned long long v,
                                     unsigned long long w) {
    asm("fma.rn.f32x2 %0, %1, %2, %0;" : "+l"(acc) : "l"(v), "l"(w));
}
__device__ __forceinline__ void unpackf2(unsigned long long v, float& lo, float& hi) {
    asm("mov.b64 {%0, %1}, %2;" : "=f"(lo), "=f"(hi) : "l"(v));
}

#define CPA16(dst, src, sz) \
    asm volatile("cp.async.cg.shared.global [%0], [%1], 16, %2;" :: "r"(dst), "l"(src), "r"(sz))
#define CPA_COMMIT() asm volatile("cp.async.commit_group;" ::: "memory")
#define CPA_WAIT0()  asm volatile("cp.async.wait_group 0;" ::: "memory")

// ---------------------------------------------------------------------------
// Kernel 0: A prep: g_wtA[g][m][kk] = tf32(weight[m][g*36+kk]) for kk<36 else 0
// ---------------------------------------------------------------------------
__global__ __launch_bounds__(256) void prep_wt_kernel(const float* __restrict__ weight)
{
    int idx = blockIdx.x * 256 + threadIdx.x;       // 90112 total
    if (idx >= 16 * 128 * 44) return;
    int g   = idx / 5632;
    int rem = idx - g * 5632;
    int m   = rem / 44;
    int kk  = rem - m * 44;
    float v = (kk < 36) ? weight[m * 576 + g * 36 + kk] : 0.f;
    g_wtA[idx] = __uint_as_float(f2tf32(v));
}

// ---------------------------------------------------------------------------
// Kernel 1: offset conv (K=7, s=2, p=3), channel-split x4, f32x2 packed FMA.
// Block 256 th = 2 oc-groups x 128 th; group: 32 tx x 4 ty, 8 rows x 1 col px.
// Tile stored even/odd-column-split (stride 36) -> conflict-free stride-2 LDS.
// ---------------------------------------------------------------------------
__global__ __launch_bounds__(256) void offset_conv_kernel(
    const float* __restrict__ x,
    const float* __restrict__ w_off)
{
    __shared__ float  te[69 * 36];
    __shared__ float  to_[69 * 36];
    __shared__ float2 ws2[2 * 441];    // [group][tap][9 oc] duplicated pairs

    const int b     = blockIdx.z & 3;
    const int chunk = blockIdx.z >> 2;
    const int ox0   = blockIdx.x * 32;
    const int oy0   = blockIdx.y * 32;
    const int tid   = threadIdx.x;
    const int og    = tid >> 7;        // oc group (0: oc 0-8, 1: oc 9-17)
    const int gt    = tid & 127;
    const int tx    = gt & 31;
    const int ty    = gt >> 5;         // 0..3

    unsigned long long acc2[36];       // [rowpair 0..3][ocpair-idx p 0..8]
#pragma unroll
    for (int i = 0; i < 36; i++) acc2[i] = 0ull;

    const int iy0 = oy0 * 2 - 3;
    const int ix0 = ox0 * 2 - 3;

    for (int c = 0; c < 16; c++) {
        const int ci = chunk * 16 + c;
        const float* xp = x + ((size_t)(b * 64 + ci) << 16);
        for (int i = tid; i < 69 * 69; i += 256) {
            int r = i / 69, col = i - r * 69;
            int iy = iy0 + r, ix = ix0 + col;
            float v = 0.f;
            if (iy >= 0 && iy < 256 && ix >= 0 && ix < 256) v = xp[iy * 256 + ix];
            float* dst = (col & 1) ? to_ : te;
            dst[r * 36 + (col >> 1)] = v;
        }
        for (int i = tid; i < 882; i += 256) {
            int gi = i / 441;
            int rm = i - gi * 441;
            int t  = rm / 9;
            int p  = rm - t * 9;
            float w = w_off[((gi * 9 + p) * 64 + ci) * 49 + t];
            ws2[i] = make_float2(w, w);
        }
        __syncthreads();

#pragma unroll 1
        for (int ky = 0; ky < 7; ky++) {
#pragma unroll
            for (int kx = 0; kx < 7; kx++) {
                const int t = ky * 7 + kx;
                const float* tp = (kx & 1) ? to_ : te;
                const int cc = tx + (kx >> 1);
                unsigned long long vp[4];
#pragma unroll
                for (int rp = 0; rp < 4; rp++) {
                    const int rb = 16 * ty + 4 * rp + ky;
                    float v0 = tp[rb * 36 + cc];
                    float v1 = tp[(rb + 2) * 36 + cc];
                    vp[rp] = packf2(v0, v1);
                }
                const float2* wsp = &ws2[og * 441 + t * 9];
#pragma unroll
                for (int p = 0; p < 9; p++) {
                    unsigned long long wp = *(const unsigned long long*)(wsp + p);
#pragma unroll
                    for (int rp = 0; rp < 4; rp++)
                        fma2(acc2[rp * 9 + p], vp[rp], wp);
                }
            }
        }
        __syncthreads();
    }

    // store: acc2[rp][p] = (out[row 2rp], out[row 2rp+1]) for oc=og*9+p
    const int col = ox0 + tx;
#pragma unroll
    for (int p = 0; p < 9; p++) {
        const int oc = og * 9 + p;
        float* op = g_offp + ((size_t)((chunk * 4 + b) * 18 + oc) << 14);
#pragma unroll
        for (int rp = 0; rp < 4; rp++) {
            float a0, a1;
            unpackf2(acc2[rp * 9 + p], a0, a1);
            const int row = oy0 + ty * 8 + 2 * rp;
            op[row * 128 + col]       = a0;
            op[(row + 1) * 128 + col] = a1;
        }
    }
}

// ---------------------------------------------------------------------------
// Kernel 2: fused deformable gather + TF32 mma GEMM + bias + GN partials.
// Block = one (b,ho) row: M=128 oc x N=128 px; K = 16 groups x 40 (4ch x 9 + pad).
// B tile stride 41 (conflict-free), A stride 44 (cp.async-aligned, conflict-free).
// ---------------------------------------------------------------------------
#define WIN_OFF    0          // 2 x 13 rows x 256 = 2 x 13312 B
#define BS_OFF     26624      // 2 x 128x41 floats = 2 x 20992 B
#define AS_OFF     68608      // 1 x 128x44 floats = 22528 B
#define MW_OFF     91136      // float4[1152] = 18432 B (reused for partials)
#define MI_OFF     109568     // int[1152] = 4608 B
#define FUSED_SMEM 114176

__global__ __launch_bounds__(256, 2) void fused_kernel(
    const float* __restrict__ x,
    const float* __restrict__ b_off,
    const float* __restrict__ bias,
    float* __restrict__ out)
{
    extern __shared__ char smem[];
    const uint32_t su = smem_u32(smem);
    const int tid = threadIdx.x;
    const int wid = tid >> 5;
    const int l   = tid & 31;
    const int bx  = blockIdx.x;
    const int b   = bx >> 7;
    const int ho  = bx & 127;
    const int yb  = 2 * ho - 6;        // 13-row window: y in [yb, yb+12]

    float4*   mw = (float4*)(smem + MW_OFF);
    int*      mi = (int*)(smem + MI_OFF);
    uint32_t* BsAll = (uint32_t*)(smem + BS_OFF);

    const float* xb = x + ((size_t)b << 22);

    // ---- prefetch window(0) + A(0) ----
    {
        for (int i = tid; i < 832; i += 256) {
            const int r = i >> 6, q = i & 63;
            const int y = yb + r;
            const int yc = min(max(y, 0), 255);
            const uint32_t sz = (y >= 0 && y < 256) ? 16u : 0u;
            CPA16(su + WIN_OFF + (i << 4), xb + yc * 256 + q * 4, sz);
        }
        for (int i = tid; i < 1408; i += 256)
            CPA16(su + AS_OFF + (uint32_t)(i * 16), g_wtA + i * 4, 16u);
        CPA_COMMIT();
    }

    // ---- zero B pad columns 36..39 in both buffers ----
    for (int i = tid; i < 1024; i += 256) {
        const int buf = i >> 9;
        const int r   = i & 511;
        const int p   = r >> 2;
        const int kk  = 36 + (r & 3);
        BsAll[buf * 5248 + p * 41 + kk] = 0u;
    }

    // ---- gather metadata: 9 taps x 128 pixels ----
    for (int i = tid; i < 1152; i += 256) {
        const int tap = i >> 7;
        const int wo  = i & 127;
        const int ky  = tap / 3;
        const int kx  = tap - ky * 3;
        const int hw  = ho * 128 + wo;

        float dy = b_off[tap * 2 + 0];
        float dx = b_off[tap * 2 + 1];
#pragma unroll
        for (int p = 0; p < 4; p++) {
            dy += g_offp[((size_t)((p * 4 + b) * 18 + tap * 2 + 0) << 14) + hw];
            dx += g_offp[((size_t)((p * 4 + b) * 18 + tap * 2 + 1) << 14) + hw];
        }
        const float yf = (float)(2 * ho - 1 + ky) + dy;
        const float xf = (float)(2 * wo - 1 + kx) + dx;
        const float y0f = floorf(yf), x0f = floorf(xf);
        const int y0 = (int)y0f, x0 = (int)x0f;
        const float wy1 = yf - y0f, wy0 = 1.f - wy1;
        const float wx1 = xf - x0f, wx0 = 1.f - wx1;

        float4 w;
        w.x = ((y0 >= 0) & (y0 < 256))         ? wy0 : 0.f;
        w.y = ((y0 + 1 >= 0) & (y0 + 1 < 256)) ? wy1 : 0.f;
        w.z = ((x0 >= 0) & (x0 < 256))         ? wx0 : 0.f;
        w.w = ((x0 + 1 >= 0) & (x0 + 1 < 256)) ? wx1 : 0.f;
        mw[i] = w;

        int wy = min(max(y0 - yb, 0), 11);
        const int x0c = min(max(x0, 0), 255);
        const int x1c = min(max(x0 + 1, 0), 255);
        mi[i] = (wy * 256 + x0c) | ((x1c - x0c) << 16);
    }

    // ---- accumulators ----
    float acc[4][4][4];
#pragma unroll
    for (int i = 0; i < 4; i++)
#pragma unroll
        for (int j = 0; j < 4; j++)
#pragma unroll
            for (int q = 0; q < 4; q++) acc[i][j][q] = 0.f;

    const int mg = wid & 1;        // m-half: rows mg*64..+63
    const int ng = wid >> 1;       // n-group: cols ng*32..+31
    const int lq = l >> 2;         // 0..7
    const int lr = l & 3;          // 0..3

    // ---- mainloop over 64 channels (16 groups of 4) ----
    for (int c = 0; c < 64; c++) {
        CPA_WAIT0();
        __syncthreads();   // window(c)/A ready; prior gathers & mma done block-wide

        if (c + 1 < 64) {
            const float* xc = xb + ((size_t)(c + 1) << 16);
            const uint32_t wdst = su + WIN_OFF + (uint32_t)(((c + 1) & 1) * 13312);
            for (int i = tid; i < 832; i += 256) {
                const int r = i >> 6, q = i & 63;
                const int y = yb + r;
                const int yc = min(max(y, 0), 255);
                const uint32_t sz = (y >= 0 && y < 256) ? 16u : 0u;
                CPA16(wdst + (i << 4), xc + yc * 256 + q * 4, sz);
            }
            if ((c & 3) == 0 && c > 0) {     // load A(group g=c>>2); A(g-1) done
                const float* asrc = g_wtA + (size_t)(c >> 2) * 5632;
                for (int i = tid; i < 1408; i += 256)
                    CPA16(su + AS_OFF + (uint32_t)(i * 16), asrc + i * 4, 16u);
            }
            CPA_COMMIT();
        }

        // gather channel c into group B buffer, columns 9*(c&3)+tap
        const float* win = (const float*)(smem + WIN_OFF + (c & 1) * 13312);
        uint32_t* Bs = BsAll + ((c >> 2) & 1) * 5248;
        const int colbase = 9 * (c & 3);
        for (int i = tid; i < 1152; i += 256) {
            const float4 w = mw[i];
            const int mm = mi[i];
            const int i00 = mm & 0xFFFF;
            const int i01 = i00 + (mm >> 16);
            const float top = w.z * win[i00]       + w.w * win[i01];
            const float bot = w.z * win[i00 + 256] + w.w * win[i01 + 256];
            const int wo  = i & 127;
            const int tap = i >> 7;
            Bs[wo * 41 + colbase + tap] = f2tf32(w.x * top + w.y * bot);
        }

        if ((c & 3) == 3) {
            __syncthreads();   // group B tile complete
            const uint32_t* As = (const uint32_t*)(smem + AS_OFF);
#pragma unroll
            for (int ks = 0; ks < 5; ks++) {
                const int k0 = ks * 8;
                uint32_t a0[4], a1[4], a2[4], a3[4], b0[4], b1[4];
#pragma unroll
                for (int mt = 0; mt < 4; mt++) {
                    const int row = mg * 64 + mt * 16 + lq;
                    a0[mt] = As[row * 44 + k0 + lr];
                    a1[mt] = As[(row + 8) * 44 + k0 + lr];
                    a2[mt] = As[row * 44 + k0 + 4 + lr];
                    a3[mt] = As[(row + 8) * 44 + k0 + 4 + lr];
                }
#pragma unroll
                for (int nt = 0; nt < 4; nt++) {
                    const int nr = ng * 32 + nt * 8 + lq;
                    b0[nt] = Bs[nr * 41 + k0 + lr];
                    b1[nt] = Bs[nr * 41 + k0 + 4 + lr];
                }
#pragma unroll
                for (int mt = 0; mt < 4; mt++)
#pragma unroll
                    for (int nt = 0; nt < 4; nt++)
                        mma_tf32(acc[mt][nt], a0[mt], a1[mt], a2[mt], a3[mt],
                                 b0[nt], b1[nt]);
            }
        }
    }

    // ---- epilogue: bias, store, GN partials ----
    __syncthreads();                       // metadata region reusable
    float* ps = (float*)(smem + MW_OFF);   // [8 warps][8 slots]
    float* pq = ps + 64;

#pragma unroll
    for (int mt = 0; mt < 4; mt++) {
        const int m0 = mg * 64 + mt * 16 + lq;
        const float bv0 = bias[m0];
        const float bv1 = bias[m0 + 8];
        float s0 = 0.f, q0 = 0.f, s1 = 0.f, q1 = 0.f;
#pragma unroll
        for (int nt = 0; nt < 4; nt++) {
            const int col = ng * 32 + nt * 8 + 2 * lr;
            float v0 = acc[mt][nt][0] + bv0;
            float v1 = acc[mt][nt][1] + bv0;
            float v2 = acc[mt][nt][2] + bv1;
            float v3 = acc[mt][nt][3] + bv1;
            s0 += v0 + v1; q0 += v0 * v0 + v1 * v1;
            s1 += v2 + v3; q1 += v2 * v2 + v3 * v3;
            *(float2*)(out + (((size_t)(b * 128 + m0)) << 14) + ho * 128 + col)
                = make_float2(v0, v1);
            *(float2*)(out + (((size_t)(b * 128 + m0 + 8)) << 14) + ho * 128 + col)
                = make_float2(v2, v3);
        }
#pragma unroll
        for (int off = 16; off > 0; off >>= 1) {
            s0 += __shfl_xor_sync(0xffffffffu, s0, off);
            q0 += __shfl_xor_sync(0xffffffffu, q0, off);
            s1 += __shfl_xor_sync(0xffffffffu, s1, off);
            q1 += __shfl_xor_sync(0xffffffffu, q1, off);
        }
        if (l == 0) {
            ps[wid * 8 + mt * 2 + 0] = s0;
            pq[wid * 8 + mt * 2 + 0] = q0;
            ps[wid * 8 + mt * 2 + 1] = s1;
            pq[wid * 8 + mt * 2 + 1] = q1;
        }
    }
    __syncthreads();
    if (tid < 16) {
        const int g = tid;
        const int gm = g >> 3;
        const int slot = g & 7;
        float S = 0.f, Q = 0.f;
#pragma unroll
        for (int j = 0; j < 4; j++) {
            const int w = gm + j * 2;
            S += ps[w * 8 + slot];
            Q += pq[w * 8 + slot];
        }
        g_psum[bx * 16 + g] = S;
        g_psq [bx * 16 + g] = Q;
    }
}

// ---------------------------------------------------------------------------
// Kernel 3: GroupNorm finalize.
// ---------------------------------------------------------------------------
__global__ __launch_bounds__(256) void gn_final_kernel(
    float* __restrict__ out,
    const float* __restrict__ gamma,
    const float* __restrict__ beta)
{
    __shared__ float rs[128], rq[128];
    const int tid  = threadIdx.x;
    const int g64  = blockIdx.x >> 3;
    const int part = blockIdx.x & 7;
    const int b    = g64 >> 4;
    const int g    = g64 & 15;

    if (tid < 128) {
        rs[tid] = g_psum[(b * 128 + tid) * 16 + g];
        rq[tid] = g_psq [(b * 128 + tid) * 16 + g];
    }
    __syncthreads();
    for (int s = 64; s > 0; s >>= 1) {
        if (tid < s) { rs[tid] += rs[tid + s]; rq[tid] += rq[tid + s]; }
        __syncthreads();
    }
    const float mu   = rs[0] * (1.f / 131072.f);
    const float var  = rq[0] * (1.f / 131072.f) - mu * mu;
    const float rsig = rsqrtf(var + 1e-5f);

    const int ch = g * 8 + part;
    const float ga = gamma[ch] * rsig;
    const float be = beta[ch] - mu * ga;

    float4* p = (float4*)(out + (((size_t)(b * 128 + ch)) << 14));
    for (int i = tid; i < 4096; i += 256) {
        float4 v = p[i];
        v.x = v.x * ga + be; v.y = v.y * ga + be;
        v.z = v.z * ga + be; v.w = v.w * ga + be;
        p[i] = v;
    }
}

// ---------------------------------------------------------------------------
extern "C" void kernel_launch(void* const* d_in, const int* in_sizes, int n_in,
                              void* d_out, int out_size)
{
    const float* x      = (const float*)d_in[0];
    const float* w_off  = (const float*)d_in[1];
    const float* b_off  = (const float*)d_in[2];
    const float* weight = (const float*)d_in[3];
    const float* bias   = (const float*)d_in[4];
    const float* gamma  = (const float*)d_in[5];
    const float* beta   = (const float*)d_in[6];
    float* out = (float*)d_out;

    cudaFuncSetAttribute(fused_kernel,
                         cudaFuncAttributeMaxDynamicSharedMemorySize, FUSED_SMEM);

    prep_wt_kernel<<<352, 256>>>(weight);
    offset_conv_kernel<<<dim3(4, 4, 16), 256>>>(x, w_off);
    fused_kernel<<<512, 256, FUSED_SMEM>>>(x, b_off, bias, out);
    gn_final_kernel<<<512, 256>>>(out, gamma, beta);
}